// round 13
// baseline (speedup 1.0000x reference)
#include <cuda_runtime.h>
#include <cuda_fp16.h>
#include <math.h>
#include <stdint.h>

#define D_MODEL     256
#define EXPERT_DIM  512
#define NUM_EXPERTS 8
#define T_TOKENS    4096
#define TILE_T      64
#define EGRID       148
#define ETHREADS    512

// u32 (half2) strides
#define XS_U32      132       // 132 % 32 == 4 -> ldmatrix conflict-free
#define HS_U32      260       // full H row (256 data + 4 pad), 260 % 32 == 4
#define W1R_U32     72
#define W2R_U32     264

#define W1STG_U     (128 * W1R_U32)         // 9216 u32 = 36864 B
#define W2STG_U     (32 * W2R_U32)          // 8448 u32 = 33792 B
#define EXPERT_U    (8 * W1STG_U + 8 * W2STG_U)   // 141312
#define NSLOT       3
#define NSTAGE      16                      // 8 W1 stages then 8 W2 stages
#define SLOT_U32    W1STG_U

#define XS_OFF      0
#define HS_OFF      (XS_OFF + TILE_T * XS_U32)          // 8448
#define WST_OFF     (HS_OFF + TILE_T * HS_U32)          // 25088 (100352 B, 128-mult)
#define CTRL_OFF    (WST_OFF + NSLOT * SLOT_U32)        // 52736
#define SMEM_U32    (CTRL_OFF + 256)
#define SMEM_BYTES  (SMEM_U32 * 4)                      // 211968 B

// ---- device scratch ----
__device__ int      g_cnt[NUM_EXPERTS];
__device__ int      g_tok [NUM_EXPERTS][T_TOKENS];
__device__ float    g_wt  [NUM_EXPERTS][T_TOKENS];
__device__ int      g_slot[NUM_EXPERTS][T_TOKENS];
__device__ float    g_scratch[2][T_TOKENS][D_MODEL];
__device__ __align__(128) uint32_t g_Wblob[NUM_EXPERTS * EXPERT_U];
__device__ int      g_done;
__device__ int      g_done2;

// ---------------------------------------------------------------------------
__device__ __forceinline__ uint32_t pack_h2(float lo, float hi) {
    __half2 h;
    h.x = __float2half_rn(lo);
    h.y = __float2half_rn(hi);
    return *reinterpret_cast<uint32_t*>(&h);
}

__device__ __forceinline__ void mma_f16(float c[4], const uint32_t a[4],
                                        uint32_t b0, uint32_t b1) {
    asm volatile(
        "mma.sync.aligned.m16n8k16.row.col.f32.f16.f16.f32 "
        "{%0,%1,%2,%3}, {%4,%5,%6,%7}, {%8,%9}, {%0,%1,%2,%3};\n"
        : "+f"(c[0]), "+f"(c[1]), "+f"(c[2]), "+f"(c[3])
        : "r"(a[0]), "r"(a[1]), "r"(a[2]), "r"(a[3]), "r"(b0), "r"(b1));
}

__device__ __forceinline__ void ldsm_x4(uint32_t a[4], uint32_t addr) {
    asm volatile(
        "ldmatrix.sync.aligned.m8n8.x4.shared.b16 {%0,%1,%2,%3}, [%4];"
        : "=r"(a[0]), "=r"(a[1]), "=r"(a[2]), "=r"(a[3]) : "r"(addr));
}

#define MBAR_INIT(mb, n)  asm volatile("mbarrier.init.shared.b64 [%0], %1;" :: "r"(mb), "r"(n) : "memory")
#define MBAR_EXPECT_TX(mb, tx) asm volatile("mbarrier.arrive.expect_tx.shared.b64 _, [%0], %1;" :: "r"(mb), "r"(tx) : "memory")
#define MBAR_ARRIVE(mb)   asm volatile("mbarrier.arrive.shared.b64 _, [%0];" :: "r"(mb) : "memory")

__device__ __forceinline__ void cp_bulk(uint32_t dst, const void* src,
                                        uint32_t bytes, uint32_t mbar) {
    asm volatile(
        "cp.async.bulk.shared::cta.global.mbarrier::complete_tx::bytes "
        "[%0], [%1], %2, [%3];"
        :: "r"(dst), "l"(src), "r"(bytes), "r"(mbar) : "memory");
}

#define MBAR_WAIT(mb, ph) do { \
    uint32_t _mb = (mb), _ph = (ph), _done; \
    asm volatile("{\n\t.reg .pred p;\n\t" \
        "mbarrier.try_wait.parity.acquire.cta.shared::cta.b64 p, [%1], %2;\n\t" \
        "selp.b32 %0, 1, 0, p;\n\t}" : "=r"(_done) : "r"(_mb), "r"(_ph) : "memory"); \
    if (!_done) { \
        asm volatile("{\n\t.reg .pred P1;\n\t" \
            "WL_%=:\n\t" \
            "mbarrier.try_wait.parity.acquire.cta.shared::cta.b64 P1, [%0], %1, 0x989680;\n\t" \
            "@P1 bra.uni WD_%=;\n\t" \
            "bra.uni WL_%=;\n\t" \
            "WD_%=:\n\t}" :: "r"(_mb), "r"(_ph) : "memory"); \
    } \
} while (0)

// ---------------------------------------------------------------------------
// Fused init: [0,512) route; [512,2560) pack W1 -> blob; [2560,4608) pack W2.
__global__ void init_kernel(const float* __restrict__ x,
                            const float* __restrict__ Wg,
                            const float* __restrict__ bg,
                            const float* __restrict__ bias,
                            const float* __restrict__ W1,
                            const float* __restrict__ W2) {
    int bid = blockIdx.x, tid = threadIdx.x;

    if (bid < 512) {
        int warp = (bid * 256 + tid) >> 5;
        int lane = tid & 31;
        int t = warp;
        const float* xr = x + (size_t)t * D_MODEL;
        float acc[NUM_EXPERTS];
#pragma unroll
        for (int e = 0; e < NUM_EXPERTS; e++) acc[e] = 0.f;
#pragma unroll
        for (int j = 0; j < D_MODEL / 32; j++) {
            int k = lane + j * 32;
            float xv = xr[k];
            const float4* wrow = (const float4*)(Wg + (size_t)k * NUM_EXPERTS);
            float4 w0 = wrow[0], w1 = wrow[1];
            acc[0] += xv * w0.x; acc[1] += xv * w0.y;
            acc[2] += xv * w0.z; acc[3] += xv * w0.w;
            acc[4] += xv * w1.x; acc[5] += xv * w1.y;
            acc[6] += xv * w1.z; acc[7] += xv * w1.w;
        }
#pragma unroll
        for (int e = 0; e < NUM_EXPERTS; e++)
#pragma unroll
            for (int off = 16; off > 0; off >>= 1)
                acc[e] += __shfl_xor_sync(0xffffffffu, acc[e], off);
        if (lane == 0) {
            float best = -INFINITY, second = -INFINITY;
            int b0 = 0, b1i = 0;
#pragma unroll
            for (int e = 0; e < NUM_EXPERTS; e++) {
                float v = acc[e] + bg[e] + bias[e];
                if (v > best)        { second = best; b1i = b0; best = v; b0 = e; }
                else if (v > second) { second = v; b1i = e; }
            }
            float e1  = expf(second - best);
            float inv = 1.f / (1.f + e1);
            int p0 = atomicAdd(&g_cnt[b0], 1);
            g_tok[b0][p0] = t; g_wt[b0][p0] = inv;      g_slot[b0][p0] = 0;
            int p1 = atomicAdd(&g_cnt[b1i], 1);
            g_tok[b1i][p1] = t; g_wt[b1i][p1] = e1 * inv; g_slot[b1i][p1] = 1;
        }
    } else if (bid < 2560) {
        // W1 -> blob: j over 8*128*512 (e, k2, h); stage c = h>>6
        int j = (bid - 512) * 256 + tid;
        int h  = j & 511;
        int k2 = (j >> 9) & 127;
        int e  = j >> 16;
        const float* src = W1 + (size_t)e * 131072 + (size_t)(2 * k2) * 512 + h;
        int c = h >> 6, col = h & 63;
        g_Wblob[(size_t)e * EXPERT_U + c * W1STG_U + k2 * W1R_U32 + col] =
            pack_h2(src[0], src[512]);
    } else {
        // W2 -> blob: j over 8*256*256 (e, k2, d); stage c = k2>>5
        int j = (bid - 2560) * 256 + tid;
        int d  = j & 255;
        int k2 = (j >> 8) & 255;
        int e  = j >> 16;
        const float* src = W2 + (size_t)e * 131072 + (size_t)(2 * k2) * 256 + d;
        int c = k2 >> 5, k2l = k2 & 31;
        g_Wblob[(size_t)e * EXPERT_U + 8 * W1STG_U + c * W2STG_U
                + k2l * W2R_U32 + d] = pack_h2(src[0], src[256]);
    }
}

// ---------------------------------------------------------------------------
// 148 blocks x 512 threads (16 warps = 2m x 8n). Two phases per item:
// phase1 computes FULL H into SMEM (no inter-warp deps), phase2 GEMM2 K=512.
// Weight slots guarded by full/empty mbarriers -> warps skew freely.
__global__ void __launch_bounds__(ETHREADS, 1)
expert_kernel(const float* __restrict__ x,
              const float* __restrict__ b1,
              const float* __restrict__ b2,
              float* __restrict__ out) {
    extern __shared__ uint32_t sm[];
    uint32_t* Xs  = sm + XS_OFF;        // [64][132]
    uint32_t* Hs  = sm + HS_OFF;        // [64][260]  full H in half2
    uint32_t* Wst = sm + WST_OFF;       // [3][9216]
    uint64_t* mbv = (uint64_t*)(sm + CTRL_OFF);   // [0..2] full, [3..5] empty
    int*   s_tok  = (int*)(sm + CTRL_OFF + 16);
    float* s_wt   = (float*)(s_tok + TILE_T);
    int*   s_slot = (int*)(s_wt + TILE_T);

    int tid  = threadIdx.x;
    int wid  = tid >> 5;
    int wm   = wid >> 3;        // 0..1
    int wn   = wid & 7;         // 0..7
    int lane = tid & 31;
    int g = lane >> 2, t = lane & 3;

    uint32_t wst_sa  = (uint32_t)__cvta_generic_to_shared(Wst);
    uint32_t xs_sa   = (uint32_t)__cvta_generic_to_shared(Xs);
    uint32_t hs_sa   = (uint32_t)__cvta_generic_to_shared(Hs);
    uint32_t mbar_sa = (uint32_t)__cvta_generic_to_shared(mbv);

    int lrow = lane & 15;
    int lcol = (lane >> 4) * 16;
    uint32_t xa0 = xs_sa + (uint32_t)((wm * 32 + lrow) * (XS_U32 * 4)) + lcol;
    uint32_t xa1 = xa0 + 16 * (XS_U32 * 4);
    uint32_t ha0 = hs_sa + (uint32_t)((wm * 32 + lrow) * (HS_U32 * 4)) + lcol;
    uint32_t ha1 = ha0 + 16 * (HS_U32 * 4);

    if (tid == 0) {
#pragma unroll
        for (int i = 0; i < NSLOT; i++) {
            MBAR_INIT(mbar_sa + i * 8, 1);                 // full: 1 (expect_tx)
            MBAR_INIT(mbar_sa + (NSLOT + i) * 8, 16);      // empty: 16 warps
        }
    }
    __syncthreads();

    // inline scheduler
    int cnt[NUM_EXPERTS], off[NUM_EXPERTS + 1];
    off[0] = 0;
#pragma unroll
    for (int e = 0; e < NUM_EXPERTS; e++) {
        cnt[e] = g_cnt[e];
        off[e + 1] = off[e] + (cnt[e] + TILE_T - 1) / TILE_T;
    }
    int total = off[NUM_EXPERTS];

    int gs = 0;   // absolute stage counter

    for (int it = blockIdx.x; it < total; it += EGRID) {
        int e = 0;
#pragma unroll
        for (int k = 1; k < NUM_EXPERTS; k++)
            if (it >= off[k]) e = k;
        int start = (it - off[e]) * TILE_T;
        int m = min(TILE_T, cnt[e] - start);

        const uint32_t* blob = g_Wblob + (size_t)e * EXPERT_U;
        const float* b1e = b1 + e * EXPERT_DIM;
        const float* b2e = b2 + e * D_MODEL;

        // producer: stage s (0..15) at absolute index a. Waits slot-empty.
        auto issue_stage = [&](int a, int s) {      // tid 0 only
            int slot = a % NSLOT;
            if (a >= NSLOT)
                MBAR_WAIT(mbar_sa + (NSLOT + slot) * 8, ((a / NSLOT) - 1) & 1);
            uint32_t dst = wst_sa + (uint32_t)(slot * SLOT_U32) * 4u;
            const uint32_t* src;
            uint32_t bytes;
            if (s < 8) { src = blob + s * W1STG_U;                      bytes = W1STG_U * 4u; }
            else       { src = blob + 8 * W1STG_U + (s - 8) * W2STG_U;  bytes = W2STG_U * 4u; }
            uint32_t mbf = mbar_sa + slot * 8;
            MBAR_EXPECT_TX(mbf, bytes);
            cp_bulk(dst, src, bytes, mbf);
        };

        __syncthreads();     // item boundary: Xs/Hs/s_tok reuse safe
        if (tid < TILE_T) {
            if (tid < m) {
                s_tok[tid]  = g_tok [e][start + tid];
                s_wt[tid]   = g_wt  [e][start + tid];
                s_slot[tid] = g_slot[e][start + tid];
            } else {
                s_tok[tid] = 0; s_wt[tid] = 0.f; s_slot[tid] = 0;
            }
        }
        if (tid == 0) {
            issue_stage(gs + 0, 0);
            issue_stage(gs + 1, 1);
            issue_stage(gs + 2, 2);
        }
        __syncthreads();     // s_tok visible

        // gather X tile -> half2 pairs
#pragma unroll
        for (int i = 0; i < 8; i++) {
            int idx = tid + i * ETHREADS;
            int row = idx >> 6, q = idx & 63;
            float4 v = make_float4(0.f, 0.f, 0.f, 0.f);
            if (row < m)
                v = ((const float4*)(x + (size_t)s_tok[row] * D_MODEL))[q];
            uint2 p;
            p.x = pack_h2(v.x, v.y);
            p.y = pack_h2(v.z, v.w);
            *((uint2*)&Xs[row * XS_U32 + q * 2]) = p;
        }
        __syncthreads();     // Xs visible

        // ================= PHASE 1: H = relu(X @ W1 + b1), all 512 cols ====
        for (int c = 0; c < 8; c++) {
            int a = gs + c;
            int slot = a % NSLOT;
            MBAR_WAIT(mbar_sa + slot * 8, (a / NSLOT) & 1);
            const uint32_t* Ws1 = Wst + slot * SLOT_U32;

            float c1[2][4];
#pragma unroll
            for (int mt = 0; mt < 2; mt++)
#pragma unroll
                for (int r = 0; r < 4; r++) c1[mt][r] = 0.f;
            int col1 = wn * 8 + g;
#pragma unroll
            for (int ks = 0; ks < 16; ks++) {
                uint32_t a0[4], a1[4];
                ldsm_x4(a0, xa0 + ks * 32);
                ldsm_x4(a1, xa1 + ks * 32);
                uint32_t b0 = Ws1[(ks * 8 + t) * W1R_U32 + col1];
                uint32_t bv = Ws1[(ks * 8 + t + 4) * W1R_U32 + col1];
                mma_f16(c1[0], a0, b0, bv);
                mma_f16(c1[1], a1, b0, bv);
            }
            if (lane == 0) MBAR_ARRIVE(mbar_sa + (NSLOT + slot) * 8);
            if (tid == 0 && c + NSLOT < NSTAGE) issue_stage(a + NSLOT, c + NSLOT);

            // bias + relu -> own Hs region (no inter-warp dependency)
            float bv0 = b1e[c * 64 + wn * 8 + 2 * t];
            float bv1 = b1e[c * 64 + wn * 8 + 2 * t + 1];
            int k2b = c * 32 + wn * 4 + t;
#pragma unroll
            for (int mt = 0; mt < 2; mt++) {
                int r0 = wm * 32 + mt * 16 + g;
                Hs[r0 * HS_U32 + k2b] =
                    pack_h2(fmaxf(c1[mt][0] + bv0, 0.f),
                            fmaxf(c1[mt][1] + bv1, 0.f));
                Hs[(r0 + 8) * HS_U32 + k2b] =
                    pack_h2(fmaxf(c1[mt][2] + bv0, 0.f),
                            fmaxf(c1[mt][3] + bv1, 0.f));
            }
        }

        __syncthreads();     // phase boundary: full H visible to all warps

        // ================= PHASE 2: out = H @ W2, K=512 ====================
        float acc2[2][4][4];
#pragma unroll
        for (int mt = 0; mt < 2; mt++)
#pragma unroll
            for (int f = 0; f < 4; f++)
#pragma unroll
                for (int r = 0; r < 4; r++) acc2[mt][f][r] = 0.f;

        for (int c = 0; c < 8; c++) {
            int s = 8 + c;
            int a = gs + s;
            int slot = a % NSLOT;
            MBAR_WAIT(mbar_sa + slot * 8, (a / NSLOT) & 1);
            const uint32_t* Ws2 = Wst + slot * SLOT_U32;

#pragma unroll
            for (int ks = 0; ks < 4; ks++) {
                uint32_t a0[4], a1[4];
                ldsm_x4(a0, ha0 + c * 128 + ks * 32);
                ldsm_x4(a1, ha1 + c * 128 + ks * 32);
#pragma unroll
                for (int f = 0; f < 4; f++) {
                    int col = wn * 32 + 8 * f + g;
                    uint32_t b0 = Ws2[(ks * 8 + t) * W2R_U32 + col];
                    uint32_t bv = Ws2[(ks * 8 + t + 4) * W2R_U32 + col];
                    mma_f16(acc2[0][f], a0, b0, bv);
                    mma_f16(acc2[1][f], a1, b0, bv);
                }
            }
            if (lane == 0) MBAR_ARRIVE(mbar_sa + (NSLOT + slot) * 8);
            if (tid == 0 && s + NSLOT < NSTAGE) issue_stage(a + NSLOT, s + NSLOT);
        }
        gs += NSTAGE;

        // ---- epilogue: scratch[slot][tok][col] = w * (acc + b2) ----
#pragma unroll
        for (int mt = 0; mt < 2; mt++) {
#pragma unroll
            for (int hr = 0; hr < 2; hr++) {
                int r = wm * 32 + mt * 16 + g + 8 * hr;
                if (r < m) {
                    float wgt = s_wt[r];
                    float* op = &g_scratch[s_slot[r]][s_tok[r]][0];
#pragma unroll
                    for (int f = 0; f < 4; f++) {
                        int col = wn * 32 + 8 * f + 2 * t;
                        float2 o;
                        o.x = wgt * (acc2[mt][f][2 * hr + 0] + b2e[col]);
                        o.y = wgt * (acc2[mt][f][2 * hr + 1] + b2e[col + 1]);
                        *((float2*)(op + col)) = o;
                    }
                }
            }
        }
    }

    // ================= spin barrier + fused combine =================
    __threadfence();
    __syncthreads();
    if (tid == 0) {
        atomicAdd(&g_done, 1);
        while (*((volatile int*)&g_done) < EGRID) { }
    }
    __syncthreads();
    __threadfence();

    const float4* s0 = (const float4*)g_scratch[0];
    const float4* s1 = (const float4*)g_scratch[1];
    float4* o4 = (float4*)out;
    const int N4 = T_TOKENS * D_MODEL / 4;
    for (int i = blockIdx.x * ETHREADS + tid; i < N4; i += EGRID * ETHREADS) {
        float4 a = s0[i], b = s1[i];
        float4 o;
        o.x = a.x + b.x; o.y = a.y + b.y; o.z = a.z + b.z; o.w = a.w + b.w;
        o4[i] = o;
    }

    // ---- last block resets counters for next graph replay ----
    __threadfence();
    __syncthreads();
    if (tid == 0) {
        int v = atomicAdd(&g_done2, 1);
        if (v == EGRID - 1) {
            g_done = 0; g_done2 = 0;
#pragma unroll
            for (int e = 0; e < NUM_EXPERTS; e++) g_cnt[e] = 0;
        }
    }
}

// ---------------------------------------------------------------------------
extern "C" void kernel_launch(void* const* d_in, const int* in_sizes, int n_in,
                              void* d_out, int out_size) {
    const float* x    = (const float*)d_in[0];
    const float* Wg   = (const float*)d_in[1];
    const float* bg   = (const float*)d_in[2];
    const float* bias = (const float*)d_in[3];
    const float* W1   = (const float*)d_in[4];
    const float* b1   = (const float*)d_in[5];
    const float* W2   = (const float*)d_in[6];
    const float* b2   = (const float*)d_in[7];
    float* out = (float*)d_out;

    cudaFuncSetAttribute(expert_kernel,
                         cudaFuncAttributeMaxDynamicSharedMemorySize, SMEM_BYTES);

    init_kernel<<<4608, 256>>>(x, Wg, bg, bias, W1, W2);
    expert_kernel<<<EGRID, ETHREADS, SMEM_BYTES>>>(x, b1, b2, out);
}

// round 14
// speedup vs baseline: 1.5252x; 1.5252x over previous
#include <cuda_runtime.h>
#include <cuda_fp16.h>
#include <math.h>
#include <stdint.h>

#define D_MODEL     256
#define EXPERT_DIM  512
#define NUM_EXPERTS 8
#define T_TOKENS    4096
#define TILE_T      64
#define EGRID       148
#define ETHREADS    512

// u32 (half2) strides
#define XS_U32      132       // ≡4 mod 32 -> ldmatrix conflict-free
#define HS_U32      68        // per-chunk H row: 64 data + 4 pad (≡4 mod 32)
#define W1R_U32     136       // 128 data + 8 pad (bank: 8t+g, conflict-free)
#define W2R_U32     264       // 256 data + 8 pad

#define W1HSTG_U    (64 * W1R_U32)          // 8704 u32 = 34816 B
#define W2HSTG_U    (32 * W2R_U32)          // 8448 u32 = 33792 B
#define CHUNKBLOB_U (2 * W1HSTG_U + 2 * W2HSTG_U)   // 34304
#define EXPERT_U    (4 * CHUNKBLOB_U)               // 137216
#define NSLOT       3
#define NSTAGE      16                      // 4 chunks * (2 W1 + 2 W2)
#define SLOT_U32    W1HSTG_U                // 8704

#define XS_OFF      0
#define HS_OFF      (XS_OFF + TILE_T * XS_U32)          // 8448
#define WST_OFF     (HS_OFF + TILE_T * HS_U32)          // 12800 (51200 B)
#define CTRL_OFF    (WST_OFF + NSLOT * SLOT_U32)        // 38912
#define SMEM_U32    (CTRL_OFF + 256)
#define SMEM_BYTES  (SMEM_U32 * 4)                      // ~156.7 KB

// ---- device scratch ----
__device__ int      g_cnt[NUM_EXPERTS];
__device__ int      g_tok [NUM_EXPERTS][T_TOKENS];
__device__ float    g_wt  [NUM_EXPERTS][T_TOKENS];
__device__ int      g_slot[NUM_EXPERTS][T_TOKENS];
__device__ float    g_scratch[2][T_TOKENS][D_MODEL];
__device__ __align__(128) uint32_t g_Wblob[NUM_EXPERTS * EXPERT_U];
__device__ int      g_done;
__device__ int      g_done2;

// ---------------------------------------------------------------------------
__device__ __forceinline__ uint32_t pack_h2(float lo, float hi) {
    __half2 h;
    h.x = __float2half_rn(lo);
    h.y = __float2half_rn(hi);
    return *reinterpret_cast<uint32_t*>(&h);
}

__device__ __forceinline__ void mma_f16(float c[4], const uint32_t a[4],
                                        uint32_t b0, uint32_t b1) {
    asm volatile(
        "mma.sync.aligned.m16n8k16.row.col.f32.f16.f16.f32 "
        "{%0,%1,%2,%3}, {%4,%5,%6,%7}, {%8,%9}, {%0,%1,%2,%3};\n"
        : "+f"(c[0]), "+f"(c[1]), "+f"(c[2]), "+f"(c[3])
        : "r"(a[0]), "r"(a[1]), "r"(a[2]), "r"(a[3]), "r"(b0), "r"(b1));
}

__device__ __forceinline__ void ldsm_x4(uint32_t a[4], uint32_t addr) {
    asm volatile(
        "ldmatrix.sync.aligned.m8n8.x4.shared.b16 {%0,%1,%2,%3}, [%4];"
        : "=r"(a[0]), "=r"(a[1]), "=r"(a[2]), "=r"(a[3]) : "r"(addr));
}

#define MBAR_INIT(mb, n)  asm volatile("mbarrier.init.shared.b64 [%0], %1;" :: "r"(mb), "r"(n) : "memory")
#define MBAR_EXPECT_TX(mb, tx) asm volatile("mbarrier.arrive.expect_tx.shared.b64 _, [%0], %1;" :: "r"(mb), "r"(tx) : "memory")

__device__ __forceinline__ void cp_bulk(uint32_t dst, const void* src,
                                        uint32_t bytes, uint32_t mbar) {
    asm volatile(
        "cp.async.bulk.shared::cta.global.mbarrier::complete_tx::bytes "
        "[%0], [%1], %2, [%3];"
        :: "r"(dst), "l"(src), "r"(bytes), "r"(mbar) : "memory");
}

#define MBAR_WAIT(mb, ph) do { \
    uint32_t _mb = (mb), _ph = (ph), _done; \
    asm volatile("{\n\t.reg .pred p;\n\t" \
        "mbarrier.try_wait.parity.acquire.cta.shared::cta.b64 p, [%1], %2;\n\t" \
        "selp.b32 %0, 1, 0, p;\n\t}" : "=r"(_done) : "r"(_mb), "r"(_ph) : "memory"); \
    if (!_done) { \
        asm volatile("{\n\t.reg .pred P1;\n\t" \
            "WL_%=:\n\t" \
            "mbarrier.try_wait.parity.acquire.cta.shared::cta.b64 P1, [%0], %1, 0x989680;\n\t" \
            "@P1 bra.uni WD_%=;\n\t" \
            "bra.uni WL_%=;\n\t" \
            "WD_%=:\n\t}" :: "r"(_mb), "r"(_ph) : "memory"); \
    } \
} while (0)

// ---------------------------------------------------------------------------
// Fused init: [0,512) route; [512,2560) pack W1 -> blob; [2560,4608) pack W2.
__global__ void init_kernel(const float* __restrict__ x,
                            const float* __restrict__ Wg,
                            const float* __restrict__ bg,
                            const float* __restrict__ bias,
                            const float* __restrict__ W1,
                            const float* __restrict__ W2) {
    int bid = blockIdx.x, tid = threadIdx.x;

    if (bid < 512) {
        int warp = (bid * 256 + tid) >> 5;
        int lane = tid & 31;
        int t = warp;
        const float* xr = x + (size_t)t * D_MODEL;
        float acc[NUM_EXPERTS];
#pragma unroll
        for (int e = 0; e < NUM_EXPERTS; e++) acc[e] = 0.f;
#pragma unroll
        for (int j = 0; j < D_MODEL / 32; j++) {
            int k = lane + j * 32;
            float xv = xr[k];
            const float4* wrow = (const float4*)(Wg + (size_t)k * NUM_EXPERTS);
            float4 w0 = wrow[0], w1 = wrow[1];
            acc[0] += xv * w0.x; acc[1] += xv * w0.y;
            acc[2] += xv * w0.z; acc[3] += xv * w0.w;
            acc[4] += xv * w1.x; acc[5] += xv * w1.y;
            acc[6] += xv * w1.z; acc[7] += xv * w1.w;
        }
#pragma unroll
        for (int e = 0; e < NUM_EXPERTS; e++)
#pragma unroll
            for (int off = 16; off > 0; off >>= 1)
                acc[e] += __shfl_xor_sync(0xffffffffu, acc[e], off);
        if (lane == 0) {
            float best = -INFINITY, second = -INFINITY;
            int b0 = 0, b1i = 0;
#pragma unroll
            for (int e = 0; e < NUM_EXPERTS; e++) {
                float v = acc[e] + bg[e] + bias[e];
                if (v > best)        { second = best; b1i = b0; best = v; b0 = e; }
                else if (v > second) { second = v; b1i = e; }
            }
            float e1  = expf(second - best);
            float inv = 1.f / (1.f + e1);
            int p0 = atomicAdd(&g_cnt[b0], 1);
            g_tok[b0][p0] = t; g_wt[b0][p0] = inv;      g_slot[b0][p0] = 0;
            int p1 = atomicAdd(&g_cnt[b1i], 1);
            g_tok[b1i][p1] = t; g_wt[b1i][p1] = e1 * inv; g_slot[b1i][p1] = 1;
        }
    } else if (bid < 2560) {
        // W1 -> blob: j over 8*128*512 (e, k2, h)
        int j = (bid - 512) * 256 + tid;
        int h  = j & 511;
        int k2 = (j >> 9) & 127;
        int e  = j >> 16;
        const float* src = W1 + (size_t)e * 131072 + (size_t)(2 * k2) * 512 + h;
        int c = h >> 7, col = h & 127;
        int kh = k2 >> 6, k2l = k2 & 63;
        g_Wblob[(size_t)e * EXPERT_U + c * CHUNKBLOB_U + kh * W1HSTG_U
                + k2l * W1R_U32 + col] = pack_h2(src[0], src[512]);
    } else {
        // W2 -> blob: j over 8*256*256 (e, k2, d)
        int j = (bid - 2560) * 256 + tid;
        int d  = j & 255;
        int k2 = (j >> 8) & 255;
        int e  = j >> 16;
        const float* src = W2 + (size_t)e * 131072 + (size_t)(2 * k2) * 256 + d;
        int c = k2 >> 6, k2c = k2 & 63;
        int kh = k2c >> 5, k2l = k2c & 31;
        g_Wblob[(size_t)e * EXPERT_U + c * CHUNKBLOB_U + 2 * W1HSTG_U
                + kh * W2HSTG_U + k2l * W2R_U32 + d] = pack_h2(src[0], src[256]);
    }
}

// ---------------------------------------------------------------------------
// 148 blocks x 512 threads (16 warps = 2m x 8n). 4 chunks of 128 h-cols;
// 16 stages (2 W1-halves + 2 W2-halves per chunk), 3-slot TMA ring,
// one __syncthreads per stage (R11 structure).
__global__ void __launch_bounds__(ETHREADS, 1)
expert_kernel(const float* __restrict__ x,
              const float* __restrict__ b1,
              const float* __restrict__ b2,
              float* __restrict__ out) {
    extern __shared__ uint32_t sm[];
    uint32_t* Xs  = sm + XS_OFF;        // [64][132]
    uint32_t* Hs  = sm + HS_OFF;        // [64][68]  current-chunk H
    uint32_t* Wst = sm + WST_OFF;       // [3][8704]
    uint64_t* mbv = (uint64_t*)(sm + CTRL_OFF);
    int*   s_tok  = (int*)(sm + CTRL_OFF + 8);
    float* s_wt   = (float*)(s_tok + TILE_T);
    int*   s_slot = (int*)(s_wt + TILE_T);

    int tid  = threadIdx.x;
    int wid  = tid >> 5;
    int wm   = wid >> 3;        // 0..1
    int wn   = wid & 7;         // 0..7
    int lane = tid & 31;
    int g = lane >> 2, t = lane & 3;

    uint32_t wst_sa  = (uint32_t)__cvta_generic_to_shared(Wst);
    uint32_t xs_sa   = (uint32_t)__cvta_generic_to_shared(Xs);
    uint32_t hs_sa   = (uint32_t)__cvta_generic_to_shared(Hs);
    uint32_t mbar_sa = (uint32_t)__cvta_generic_to_shared(mbv);

    int lrow = lane & 15;
    int lcol = (lane >> 4) * 16;
    uint32_t xa0 = xs_sa + (uint32_t)((wm * 32 + lrow) * (XS_U32 * 4)) + lcol;
    uint32_t xa1 = xa0 + 16 * (XS_U32 * 4);
    uint32_t ha0 = hs_sa + (uint32_t)((wm * 32 + lrow) * (HS_U32 * 4)) + lcol;
    uint32_t ha1 = ha0 + 16 * (HS_U32 * 4);

    if (tid == 0) {
#pragma unroll
        for (int i = 0; i < NSLOT; i++) MBAR_INIT(mbar_sa + i * 8, 1);
    }
    __syncthreads();

    // inline scheduler
    int cnt[NUM_EXPERTS], off[NUM_EXPERTS + 1];
    off[0] = 0;
#pragma unroll
    for (int e = 0; e < NUM_EXPERTS; e++) {
        cnt[e] = g_cnt[e];
        off[e + 1] = off[e] + (cnt[e] + TILE_T - 1) / TILE_T;
    }
    int total = off[NUM_EXPERTS];

    int gs = 0;   // absolute stage counter

    for (int it = blockIdx.x; it < total; it += EGRID) {
        int e = 0;
#pragma unroll
        for (int k = 1; k < NUM_EXPERTS; k++)
            if (it >= off[k]) e = k;
        int start = (it - off[e]) * TILE_T;
        int m = min(TILE_T, cnt[e] - start);

        const uint32_t* blob = g_Wblob + (size_t)e * EXPERT_U;
        const float* b1e = b1 + e * EXPERT_DIM;
        const float* b2e = b2 + e * D_MODEL;

        // stage s (0..15): c = s>>2, j = s&3.
        //  j<2 : W1 K-half j of chunk c      (34816 B)
        //  j>=2: W2 K-half j-2 of chunk c    (33792 B)
        auto issue_stage = [&](int s) {      // tid 0 only
            int a = gs + s;
            int slot = a % NSLOT;
            int c = s >> 2, j = s & 3;
            uint32_t dst = wst_sa + (uint32_t)(slot * SLOT_U32) * 4u;
            const uint32_t* src;
            uint32_t bytes;
            if (j < 2) {
                src = blob + c * CHUNKBLOB_U + j * W1HSTG_U;
                bytes = W1HSTG_U * 4u;
            } else {
                src = blob + c * CHUNKBLOB_U + 2 * W1HSTG_U + (j - 2) * W2HSTG_U;
                bytes = W2HSTG_U * 4u;
            }
            uint32_t mb = mbar_sa + slot * 8;
            MBAR_EXPECT_TX(mb, bytes);
            cp_bulk(dst, src, bytes, mb);
        };

        __syncthreads();
        if (tid < TILE_T) {
            if (tid < m) {
                s_tok[tid]  = g_tok [e][start + tid];
                s_wt[tid]   = g_wt  [e][start + tid];
                s_slot[tid] = g_slot[e][start + tid];
            } else {
                s_tok[tid] = 0; s_wt[tid] = 0.f; s_slot[tid] = 0;
            }
        }
        if (tid == 0) { issue_stage(0); issue_stage(1); }
        __syncthreads();

        // gather X tile -> half2 pairs: 64 rows x 64 float4
#pragma unroll
        for (int i = 0; i < 8; i++) {
            int idx = tid + i * ETHREADS;
            int row = idx >> 6, q = idx & 63;
            float4 v = make_float4(0.f, 0.f, 0.f, 0.f);
            if (row < m)
                v = ((const float4*)(x + (size_t)s_tok[row] * D_MODEL))[q];
            uint2 p;
            p.x = pack_h2(v.x, v.y);
            p.y = pack_h2(v.z, v.w);
            *((uint2*)&Xs[row * XS_U32 + q * 2]) = p;
        }

        float acc2[2][4][4];
#pragma unroll
        for (int mt = 0; mt < 2; mt++)
#pragma unroll
            for (int f = 0; f < 4; f++)
#pragma unroll
                for (int r = 0; r < 4; r++) acc2[mt][f][r] = 0.f;
        float c1[2][2][4];    // [mt][f][reg], GEMM1 n-slice 16 cols

        for (int s = 0; s < NSTAGE; s++) {
            int a = gs + s;
            int slot = a % NSLOT;
            MBAR_WAIT(mbar_sa + slot * 8, (a / NSLOT) & 1);
            __syncthreads();             // all warps past stage s-1 (slot reuse + Hs)
            if (tid == 0 && s + 2 < NSTAGE) issue_stage(s + 2);

            int c = s >> 2, j = s & 3;
            const uint32_t* Ws = Wst + slot * SLOT_U32;

            if (j < 2) {
                // ====== GEMM1 K-half j: 8 ksteps, n-slice 16 cols ======
                if (j == 0) {
#pragma unroll
                    for (int mt = 0; mt < 2; mt++)
#pragma unroll
                        for (int f = 0; f < 2; f++)
#pragma unroll
                            for (int r = 0; r < 4; r++) c1[mt][f][r] = 0.f;
                }
#pragma unroll
                for (int ks = 0; ks < 8; ks++) {
                    uint32_t a0[4], a1[4];
                    ldsm_x4(a0, xa0 + (j * 8 + ks) * 32);
                    ldsm_x4(a1, xa1 + (j * 8 + ks) * 32);
#pragma unroll
                    for (int f = 0; f < 2; f++) {
                        int col = wn * 16 + 8 * f + g;
                        uint32_t b0 = Ws[(ks * 8 + t) * W1R_U32 + col];
                        uint32_t bv = Ws[(ks * 8 + t + 4) * W1R_U32 + col];
                        mma_f16(c1[0][f], a0, b0, bv);
                        mma_f16(c1[1][f], a1, b0, bv);
                    }
                }
                if (j == 1) {
                    // bias + relu -> Hs (per-chunk, 128 cols wide)
#pragma unroll
                    for (int f = 0; f < 2; f++) {
                        float bv0 = b1e[c * 128 + wn * 16 + 8 * f + 2 * t];
                        float bv1 = b1e[c * 128 + wn * 16 + 8 * f + 2 * t + 1];
                        int k2b = wn * 8 + 4 * f + t;
#pragma unroll
                        for (int mt = 0; mt < 2; mt++) {
                            int r0 = wm * 32 + mt * 16 + g;
                            Hs[r0 * HS_U32 + k2b] =
                                pack_h2(fmaxf(c1[mt][f][0] + bv0, 0.f),
                                        fmaxf(c1[mt][f][1] + bv1, 0.f));
                            Hs[(r0 + 8) * HS_U32 + k2b] =
                                pack_h2(fmaxf(c1[mt][f][2] + bv0, 0.f),
                                        fmaxf(c1[mt][f][3] + bv1, 0.f));
                        }
                    }
                }
            } else {
                // ====== GEMM2 K-half j-2: 4 ksteps, n-slice 32 cols ======
                int kh = j - 2;
#pragma unroll
                for (int ks = 0; ks < 4; ks++) {
                    uint32_t a0[4], a1[4];
                    ldsm_x4(a0, ha0 + (kh * 4 + ks) * 32);
                    ldsm_x4(a1, ha1 + (kh * 4 + ks) * 32);
#pragma unroll
                    for (int f = 0; f < 4; f++) {
                        int col = wn * 32 + 8 * f + g;
                        uint32_t b0 = Ws[(ks * 8 + t) * W2R_U32 + col];
                        uint32_t bv = Ws[(ks * 8 + t + 4) * W2R_U32 + col];
                        mma_f16(acc2[0][f], a0, b0, bv);
                        mma_f16(acc2[1][f], a1, b0, bv);
                    }
                }
            }
        }
        gs += NSTAGE;

        // ---- epilogue: scratch[slot][tok][col] = w * (acc + b2) ----
#pragma unroll
        for (int mt = 0; mt < 2; mt++) {
#pragma unroll
            for (int hr = 0; hr < 2; hr++) {
                int r = wm * 32 + mt * 16 + g + 8 * hr;
                if (r < m) {
                    float wgt = s_wt[r];
                    float* op = &g_scratch[s_slot[r]][s_tok[r]][0];
#pragma unroll
                    for (int f = 0; f < 4; f++) {
                        int col = wn * 32 + 8 * f + 2 * t;
                        float2 o;
                        o.x = wgt * (acc2[mt][f][2 * hr + 0] + b2e[col]);
                        o.y = wgt * (acc2[mt][f][2 * hr + 1] + b2e[col + 1]);
                        *((float2*)(op + col)) = o;
                    }
                }
            }
        }
    }

    // ================= spin barrier + fused combine =================
    __threadfence();
    __syncthreads();
    if (tid == 0) {
        atomicAdd(&g_done, 1);
        while (*((volatile int*)&g_done) < EGRID) { }
    }
    __syncthreads();
    __threadfence();

    const float4* s0 = (const float4*)g_scratch[0];
    const float4* s1 = (const float4*)g_scratch[1];
    float4* o4 = (float4*)out;
    const int N4 = T_TOKENS * D_MODEL / 4;
    for (int i = blockIdx.x * ETHREADS + tid; i < N4; i += EGRID * ETHREADS) {
        float4 a = s0[i], b = s1[i];
        float4 o;
        o.x = a.x + b.x; o.y = a.y + b.y; o.z = a.z + b.z; o.w = a.w + b.w;
        o4[i] = o;
    }

    // ---- last block resets counters for next graph replay ----
    __threadfence();
    __syncthreads();
    if (tid == 0) {
        int v = atomicAdd(&g_done2, 1);
        if (v == EGRID - 1) {
            g_done = 0; g_done2 = 0;
#pragma unroll
            for (int e = 0; e < NUM_EXPERTS; e++) g_cnt[e] = 0;
        }
    }
}

// ---------------------------------------------------------------------------
extern "C" void kernel_launch(void* const* d_in, const int* in_sizes, int n_in,
                              void* d_out, int out_size) {
    const float* x    = (const float*)d_in[0];
    const float* Wg   = (const float*)d_in[1];
    const float* bg   = (const float*)d_in[2];
    const float* bias = (const float*)d_in[3];
    const float* W1   = (const float*)d_in[4];
    const float* b1   = (const float*)d_in[5];
    const float* W2   = (const float*)d_in[6];
    const float* b2   = (const float*)d_in[7];
    float* out = (float*)d_out;

    cudaFuncSetAttribute(expert_kernel,
                         cudaFuncAttributeMaxDynamicSharedMemorySize, SMEM_BYTES);

    init_kernel<<<4608, 256>>>(x, Wg, bg, bias, W1, W2);
    expert_kernel<<<EGRID, ETHREADS, SMEM_BYTES>>>(x, b1, b2, out);
}